// round 1
// baseline (speedup 1.0000x reference)
#include <cuda_runtime.h>
#include <cstdint>

#define NN   100000
#define FIN  256
#define HID  128
#define NC   47
#define NCP  48

// ---------------- scratch (device globals: no allocation allowed) ----------
__device__ float g_xw [(size_t)NN * HID];   // x @ W1
__device__ float g_h  [(size_t)NN * HID];   // agg1 -> relu(h)
__device__ float g_hw [(size_t)NN * NCP];   // h @ W2 (padded to 48)
__device__ float g_agg[(size_t)NN * NCP];   // agg2 (padded)
__device__ float g_dinv[NN];                // deg -> rsqrt(deg)

typedef unsigned long long ull;

__device__ __forceinline__ ull pk2(float lo, float hi) {
    ull r; asm("mov.b64 %0,{%1,%2};" : "=l"(r) : "f"(lo), "f"(hi)); return r;
}
__device__ __forceinline__ void unpk2(ull v, float &lo, float &hi) {
    asm("mov.b64 {%0,%1},%2;" : "=f"(lo), "=f"(hi) : "l"(v));
}
__device__ __forceinline__ ull fma2(ull a, ull b, ull c) {
    ull d; asm("fma.rn.f32x2 %0,%1,%2,%3;" : "=l"(d) : "l"(a), "l"(b), "l"(c)); return d;
}
__device__ __forceinline__ void red4(float *p, float x, float y, float z, float w) {
    asm volatile("red.global.add.v4.f32 [%0], {%1,%2,%3,%4};"
                 :: "l"(p), "f"(x), "f"(y), "f"(z), "f"(w) : "memory");
}

// ---------------- degree / norm --------------------------------------------
__global__ void k_deg_init() {
    int i = blockIdx.x * blockDim.x + threadIdx.x;
    if (i < NN) g_dinv[i] = 1.0f;                 // self-loop counts once
}
__global__ void k_deg_count(const int *__restrict__ dst, int E) {
    int i = blockIdx.x * blockDim.x + threadIdx.x;
    if (i < E) atomicAdd(&g_dinv[dst[i]], 1.0f);
}
__global__ void k_dinv() {
    int i = blockIdx.x * blockDim.x + threadIdx.x;
    if (i < NN) g_dinv[i] = rsqrtf(g_dinv[i]);    // deg >= 1 always
}

// ---------------- zero scratch ----------------------------------------------
__global__ void k_zero_bufs() {
    size_t t  = (size_t)blockIdx.x * blockDim.x + threadIdx.x;
    size_t st = (size_t)gridDim.x * blockDim.x;
    float4 z  = make_float4(0.f, 0.f, 0.f, 0.f);
    size_t n1 = (size_t)NN * HID / 4;
    size_t n2 = (size_t)NN * NCP / 4;
    for (size_t i = t; i < n1; i += st) reinterpret_cast<float4 *>(g_h)[i]   = z;
    for (size_t i = t; i < n2; i += st) reinterpret_cast<float4 *>(g_agg)[i] = z;
}

// ---------------- GEMM1: g_xw = X[NN,256] @ W1[256,128] --------------------
// BM=128 BN=128 BK=16, 256 threads, 8x8 per thread via fma.rn.f32x2
__global__ __launch_bounds__(256) void k_gemm1(const float *__restrict__ X,
                                               const float *__restrict__ W) {
    __shared__ float As[16][128];   // [k][m]
    __shared__ float Bs[16][128];   // [k][n]
    const int tid = threadIdx.x;
    const int m0  = blockIdx.x * 128;
    const int ty  = tid >> 4;       // 0..15  -> rows ty*8..+7
    const int tx  = tid & 15;       // 0..15  -> cols tx*8..+7

    ull acc[8][4];
#pragma unroll
    for (int i = 0; i < 8; i++)
#pragma unroll
        for (int j = 0; j < 4; j++) acc[i][j] = 0ull;

    for (int kt = 0; kt < FIN; kt += 16) {
#pragma unroll
        for (int l = 0; l < 2; l++) {             // A tile: 512 float4
            int q = tid + l * 256;
            int r = q >> 2, c4 = q & 3;
            int row = m0 + r;
            float4 v = make_float4(0.f, 0.f, 0.f, 0.f);
            if (row < NN)
                v = *reinterpret_cast<const float4 *>(&X[(size_t)row * FIN + kt + c4 * 4]);
            As[c4 * 4 + 0][r] = v.x; As[c4 * 4 + 1][r] = v.y;
            As[c4 * 4 + 2][r] = v.z; As[c4 * 4 + 3][r] = v.w;
        }
#pragma unroll
        for (int l = 0; l < 2; l++) {             // B tile: 512 float4
            int q = tid + l * 256;
            int r = q >> 5, c4 = q & 31;
            *reinterpret_cast<float4 *>(&Bs[r][c4 * 4]) =
                *reinterpret_cast<const float4 *>(&W[(size_t)(kt + r) * HID + c4 * 4]);
        }
        __syncthreads();
#pragma unroll
        for (int kk = 0; kk < 16; kk++) {
            float4 a0 = *reinterpret_cast<float4 *>(&As[kk][ty * 8]);
            float4 a1 = *reinterpret_cast<float4 *>(&As[kk][ty * 8 + 4]);
            float4 b0 = *reinterpret_cast<float4 *>(&Bs[kk][tx * 8]);
            float4 b1 = *reinterpret_cast<float4 *>(&Bs[kk][tx * 8 + 4]);
            ull bb[4] = { pk2(b0.x, b0.y), pk2(b0.z, b0.w),
                          pk2(b1.x, b1.y), pk2(b1.z, b1.w) };
            float av[8] = { a0.x, a0.y, a0.z, a0.w, a1.x, a1.y, a1.z, a1.w };
#pragma unroll
            for (int i = 0; i < 8; i++) {
                ull aa = pk2(av[i], av[i]);
#pragma unroll
                for (int jj = 0; jj < 4; jj++) acc[i][jj] = fma2(aa, bb[jj], acc[i][jj]);
            }
        }
        __syncthreads();
    }
#pragma unroll
    for (int i = 0; i < 8; i++) {
        int row = m0 + ty * 8 + i;
        if (row < NN) {
            float o0, o1, o2, o3, o4, o5, o6, o7;
            unpk2(acc[i][0], o0, o1); unpk2(acc[i][1], o2, o3);
            unpk2(acc[i][2], o4, o5); unpk2(acc[i][3], o6, o7);
            float4 *p = reinterpret_cast<float4 *>(&g_xw[(size_t)row * HID + tx * 8]);
            p[0] = make_float4(o0, o1, o2, o3);
            p[1] = make_float4(o4, o5, o6, o7);
        }
    }
}

// ---------------- scatter layer 1: warp per edge, 128 feats ----------------
__global__ void k_scat1(const int *__restrict__ src, const int *__restrict__ dst, int E) {
    const int lane = threadIdx.x & 31;
    int w  = (blockIdx.x * blockDim.x + threadIdx.x) >> 5;
    int nw = (gridDim.x * blockDim.x) >> 5;
    for (int e = w; e < E; e += nw) {
        int s = __ldg(&src[e]);
        int d = __ldg(&dst[e]);
        float c = g_dinv[s] * g_dinv[d];
        float4 v = *reinterpret_cast<const float4 *>(&g_xw[(size_t)s * HID + lane * 4]);
        red4(&g_h[(size_t)d * HID + lane * 4], v.x * c, v.y * c, v.z * c, v.w * c);
    }
}

// ---------------- h = relu(agg1 + self_loop + b1) ---------------------------
__global__ void k_bias_relu(const float *__restrict__ b1) {
    int i = blockIdx.x * blockDim.x + threadIdx.x;   // over NN*32 float4s
    if (i >= NN * 32) return;
    int node = i >> 5, f4 = i & 31;
    float c = g_dinv[node]; c *= c;
    float4 a = *reinterpret_cast<float4 *>(&g_h[(size_t)i * 4]);
    float4 x = *reinterpret_cast<float4 *>(&g_xw[(size_t)i * 4]);
    float4 b = *reinterpret_cast<const float4 *>(&b1[f4 * 4]);
    float4 r;
    r.x = fmaxf(fmaf(x.x, c, a.x) + b.x, 0.f);
    r.y = fmaxf(fmaf(x.y, c, a.y) + b.y, 0.f);
    r.z = fmaxf(fmaf(x.z, c, a.z) + b.z, 0.f);
    r.w = fmaxf(fmaf(x.w, c, a.w) + b.w, 0.f);
    *reinterpret_cast<float4 *>(&g_h[(size_t)i * 4]) = r;
}

// ---------------- GEMM2: g_hw = h[NN,128] @ W2[128,47] (padded 48) ----------
// BM=128 BN=48 BK=16, 256 threads, TM=4 TN=6
__global__ __launch_bounds__(256) void k_gemm2(const float *__restrict__ W2) {
    __shared__ float As[16][128];   // [k][m]
    __shared__ float Bs[16][48];    // [k][n]
    const int tid = threadIdx.x;
    const int m0  = blockIdx.x * 128;
    const int ty  = tid >> 3;       // 0..31 -> rows ty*4..+3
    const int tx  = tid & 7;        // 0..7  -> cols tx*6..+5

    ull acc[4][3];
#pragma unroll
    for (int i = 0; i < 4; i++)
#pragma unroll
        for (int j = 0; j < 3; j++) acc[i][j] = 0ull;

    for (int kt = 0; kt < HID; kt += 16) {
#pragma unroll
        for (int l = 0; l < 2; l++) {             // A tile
            int q = tid + l * 256;
            int r = q >> 2, c4 = q & 3;
            int row = m0 + r;
            float4 v = make_float4(0.f, 0.f, 0.f, 0.f);
            if (row < NN)
                v = *reinterpret_cast<const float4 *>(&g_h[(size_t)row * HID + kt + c4 * 4]);
            As[c4 * 4 + 0][r] = v.x; As[c4 * 4 + 1][r] = v.y;
            As[c4 * 4 + 2][r] = v.z; As[c4 * 4 + 3][r] = v.w;
        }
#pragma unroll
        for (int l = 0; l < 3; l++) {             // B tile 16x48 (pad col 47)
            int q = tid + l * 256;
            int k = q / 48, c = q % 48;
            Bs[k][c] = (c < NC) ? W2[(size_t)(kt + k) * NC + c] : 0.f;
        }
        __syncthreads();
#pragma unroll
        for (int kk = 0; kk < 16; kk++) {
            float4 a = *reinterpret_cast<float4 *>(&As[kk][ty * 4]);
            float2 c0 = *reinterpret_cast<float2 *>(&Bs[kk][tx * 6]);
            float2 c1 = *reinterpret_cast<float2 *>(&Bs[kk][tx * 6 + 2]);
            float2 c2 = *reinterpret_cast<float2 *>(&Bs[kk][tx * 6 + 4]);
            ull bb[3] = { pk2(c0.x, c0.y), pk2(c1.x, c1.y), pk2(c2.x, c2.y) };
            float av[4] = { a.x, a.y, a.z, a.w };
#pragma unroll
            for (int i = 0; i < 4; i++) {
                ull aa = pk2(av[i], av[i]);
#pragma unroll
                for (int jj = 0; jj < 3; jj++) acc[i][jj] = fma2(aa, bb[jj], acc[i][jj]);
            }
        }
        __syncthreads();
    }
#pragma unroll
    for (int i = 0; i < 4; i++) {
        int row = m0 + ty * 4 + i;
        if (row < NN) {
            float o0, o1, o2, o3, o4, o5;
            unpk2(acc[i][0], o0, o1); unpk2(acc[i][1], o2, o3); unpk2(acc[i][2], o4, o5);
            float *p = &g_hw[(size_t)row * NCP + tx * 6];
            *reinterpret_cast<float2 *>(p)     = make_float2(o0, o1);
            *reinterpret_cast<float2 *>(p + 2) = make_float2(o2, o3);
            *reinterpret_cast<float2 *>(p + 4) = make_float2(o4, o5);
        }
    }
}

// ---------------- scatter layer 2: 12 threads per edge (48 cols) -----------
__global__ void k_scat2(const int *__restrict__ src, const int *__restrict__ dst, int E) {
    long long t  = (long long)blockIdx.x * blockDim.x + threadIdx.x;
    long long nt = (long long)gridDim.x * blockDim.x;
    long long items = (long long)E * 12;
    for (long long it = t; it < items; it += nt) {
        int e = (int)(it / 12);
        int g = (int)(it - (long long)e * 12);
        int s = __ldg(&src[e]);
        int d = __ldg(&dst[e]);
        float c = g_dinv[s] * g_dinv[d];
        float4 v = *reinterpret_cast<const float4 *>(&g_hw[(size_t)s * NCP + g * 4]);
        red4(&g_agg[(size_t)d * NCP + g * 4], v.x * c, v.y * c, v.z * c, v.w * c);
    }
}

// ---------------- final: self loop + bias + log_softmax --------------------
__global__ void k_final(const float *__restrict__ b2, float *__restrict__ out) {
    int w = (blockIdx.x * blockDim.x + threadIdx.x) >> 5;
    int lane = threadIdx.x & 31;
    if (w >= NN) return;
    float c = g_dinv[w]; c *= c;
    const float *ag = &g_agg[(size_t)w * NCP];
    const float *hw = &g_hw [(size_t)w * NCP];
    int c0 = lane, c1 = lane + 32;
    float v0 = ag[c0] + hw[c0] * c + b2[c0];
    float v1 = -1e30f;
    if (c1 < NC) v1 = ag[c1] + hw[c1] * c + b2[c1];
    float m = fmaxf(v0, v1);
#pragma unroll
    for (int off = 16; off > 0; off >>= 1)
        m = fmaxf(m, __shfl_xor_sync(0xffffffffu, m, off));
    float s = expf(v0 - m) + ((c1 < NC) ? expf(v1 - m) : 0.f);
#pragma unroll
    for (int off = 16; off > 0; off >>= 1)
        s += __shfl_xor_sync(0xffffffffu, s, off);
    float ls = logf(s) + m;
    out[(size_t)w * NC + c0] = v0 - ls;
    if (c1 < NC) out[(size_t)w * NC + c1] = v1 - ls;
}

// ---------------- launch ----------------------------------------------------
extern "C" void kernel_launch(void *const *d_in, const int *in_sizes, int n_in,
                              void *d_out, int out_size) {
    const float *x  = (const float *)d_in[0];
    const int   *ei = (const int   *)d_in[1];
    const float *W1 = (const float *)d_in[2];
    const float *b1 = (const float *)d_in[3];
    const float *W2 = (const float *)d_in[4];
    const float *b2 = (const float *)d_in[5];
    float *out = (float *)d_out;

    const int E = in_sizes[1] / 2;
    const int *src = ei;
    const int *dst = ei + E;

    k_zero_bufs<<<4736, 256>>>();
    k_deg_init<<<(NN + 255) / 256, 256>>>();
    k_deg_count<<<(E + 255) / 256, 256>>>(dst, E);
    k_dinv<<<(NN + 255) / 256, 256>>>();

    k_gemm1<<<(NN + 127) / 128, 256>>>(x, W1);
    k_scat1<<<4736, 256>>>(src, dst, E);
    k_bias_relu<<<(NN * 32 + 255) / 256, 256>>>(b1);

    k_gemm2<<<(NN + 127) / 128, 256>>>(W2);
    k_scat2<<<4736, 256>>>(src, dst, E);
    k_final<<<(NN * 32 + 255) / 256, 256>>>(b2, out);
}

// round 2
// speedup vs baseline: 1.2986x; 1.2986x over previous
#include <cuda_runtime.h>
#include <cstdint>

#define NN   100000
#define FIN  256
#define HID  128
#define NC   47
#define NCP  48
#define EMAX 2000000
#define NB   ((NN + 255) / 256)   // 391 scan blocks

// ---------------- scratch (device globals: no allocation allowed) ----------
__device__ float g_xw [(size_t)NN * HID];   // x @ W1
__device__ float g_h  [(size_t)NN * HID];   // relu(agg1 + b1)
__device__ float g_hw [(size_t)NN * NCP];   // h @ W2 (padded to 48)
__device__ float g_dinv[NN];                // rsqrt(deg)
__device__ int   g_cnt [NN];                // in-degree (no self loop)
__device__ int   g_off [NN];                // CSR row offsets (by dst)
__device__ int   g_cur [NN];                // fill cursors
__device__ int   g_csr [EMAX];              // src indices grouped by dst
__device__ int   g_bsum[512];               // scan block sums

typedef unsigned long long ull;

__device__ __forceinline__ ull pk2(float lo, float hi) {
    ull r; asm("mov.b64 %0,{%1,%2};" : "=l"(r) : "f"(lo), "f"(hi)); return r;
}
__device__ __forceinline__ void unpk2(ull v, float &lo, float &hi) {
    asm("mov.b64 {%0,%1},%2;" : "=f"(lo), "=f"(hi) : "l"(v));
}
__device__ __forceinline__ ull fma2(ull a, ull b, ull c) {
    ull d; asm("fma.rn.f32x2 %0,%1,%2,%3;" : "=l"(d) : "l"(a), "l"(b), "l"(c)); return d;
}

// ---------------- CSR build --------------------------------------------------
__global__ void k_zero_cnt() {
    int i = blockIdx.x * blockDim.x + threadIdx.x;
    if (i < NN) g_cnt[i] = 0;
}
__global__ void k_hist(const int *__restrict__ dst, int E) {
    int i = blockIdx.x * blockDim.x + threadIdx.x;
    if (i < E) atomicAdd(&g_cnt[dst[i]], 1);
}
__global__ void k_scan1() {                       // per-block sums
    __shared__ int sh[256];
    int i = blockIdx.x * 256 + threadIdx.x;
    sh[threadIdx.x] = (i < NN) ? g_cnt[i] : 0;
    __syncthreads();
#pragma unroll
    for (int o = 128; o > 0; o >>= 1) {
        if (threadIdx.x < o) sh[threadIdx.x] += sh[threadIdx.x + o];
        __syncthreads();
    }
    if (threadIdx.x == 0) g_bsum[blockIdx.x] = sh[0];
}
__global__ void k_scan2() {                       // exclusive scan of block sums
    __shared__ int sh[512];
    int t = threadIdx.x;
    int v = (t < NB) ? g_bsum[t] : 0;
    sh[t] = v;
    __syncthreads();
#pragma unroll
    for (int o = 1; o < 512; o <<= 1) {
        int u = (t >= o) ? sh[t - o] : 0;
        __syncthreads();
        sh[t] += u;
        __syncthreads();
    }
    if (t < NB) g_bsum[t] = sh[t] - v;            // exclusive
}
__global__ void k_scan3() {                       // offsets, cursors, dinv
    __shared__ int sh[256];
    int t = threadIdx.x;
    int i = blockIdx.x * 256 + t;
    int v = (i < NN) ? g_cnt[i] : 0;
    sh[t] = v;
    __syncthreads();
#pragma unroll
    for (int o = 1; o < 256; o <<= 1) {
        int u = (t >= o) ? sh[t - o] : 0;
        __syncthreads();
        sh[t] += u;
        __syncthreads();
    }
    if (i < NN) {
        int ex = g_bsum[blockIdx.x] + sh[t] - v;
        g_off[i] = ex;
        g_cur[i] = ex;
        g_dinv[i] = rsqrtf((float)(v + 1));       // +1 self loop
    }
}
__global__ void k_fill(const int *__restrict__ src, const int *__restrict__ dst, int E) {
    int i = blockIdx.x * blockDim.x + threadIdx.x;
    if (i < E) {
        int pos = atomicAdd(&g_cur[dst[i]], 1);
        g_csr[pos] = src[i];
    }
}

// ---------------- GEMM1: g_xw = X[NN,256] @ W1[256,128] --------------------
__global__ __launch_bounds__(256) void k_gemm1(const float *__restrict__ X,
                                               const float *__restrict__ W) {
    __shared__ float As[16][128];   // [k][m]
    __shared__ float Bs[16][128];   // [k][n]
    const int tid = threadIdx.x;
    const int m0  = blockIdx.x * 128;
    const int ty  = tid >> 4;
    const int tx  = tid & 15;

    ull acc[8][4];
#pragma unroll
    for (int i = 0; i < 8; i++)
#pragma unroll
        for (int j = 0; j < 4; j++) acc[i][j] = 0ull;

    for (int kt = 0; kt < FIN; kt += 16) {
#pragma unroll
        for (int l = 0; l < 2; l++) {
            int q = tid + l * 256;
            int r = q >> 2, c4 = q & 3;
            int row = m0 + r;
            float4 v = make_float4(0.f, 0.f, 0.f, 0.f);
            if (row < NN)
                v = *reinterpret_cast<const float4 *>(&X[(size_t)row * FIN + kt + c4 * 4]);
            As[c4 * 4 + 0][r] = v.x; As[c4 * 4 + 1][r] = v.y;
            As[c4 * 4 + 2][r] = v.z; As[c4 * 4 + 3][r] = v.w;
        }
#pragma unroll
        for (int l = 0; l < 2; l++) {
            int q = tid + l * 256;
            int r = q >> 5, c4 = q & 31;
            *reinterpret_cast<float4 *>(&Bs[r][c4 * 4]) =
                *reinterpret_cast<const float4 *>(&W[(size_t)(kt + r) * HID + c4 * 4]);
        }
        __syncthreads();
#pragma unroll
        for (int kk = 0; kk < 16; kk++) {
            float4 a0 = *reinterpret_cast<float4 *>(&As[kk][ty * 8]);
            float4 a1 = *reinterpret_cast<float4 *>(&As[kk][ty * 8 + 4]);
            float4 b0 = *reinterpret_cast<float4 *>(&Bs[kk][tx * 8]);
            float4 b1 = *reinterpret_cast<float4 *>(&Bs[kk][tx * 8 + 4]);
            ull bb[4] = { pk2(b0.x, b0.y), pk2(b0.z, b0.w),
                          pk2(b1.x, b1.y), pk2(b1.z, b1.w) };
            float av[8] = { a0.x, a0.y, a0.z, a0.w, a1.x, a1.y, a1.z, a1.w };
#pragma unroll
            for (int i = 0; i < 8; i++) {
                ull aa = pk2(av[i], av[i]);
#pragma unroll
                for (int jj = 0; jj < 4; jj++) acc[i][jj] = fma2(aa, bb[jj], acc[i][jj]);
            }
        }
        __syncthreads();
    }
#pragma unroll
    for (int i = 0; i < 8; i++) {
        int row = m0 + ty * 8 + i;
        if (row < NN) {
            float o0, o1, o2, o3, o4, o5, o6, o7;
            unpk2(acc[i][0], o0, o1); unpk2(acc[i][1], o2, o3);
            unpk2(acc[i][2], o4, o5); unpk2(acc[i][3], o6, o7);
            float4 *p = reinterpret_cast<float4 *>(&g_xw[(size_t)row * HID + tx * 8]);
            p[0] = make_float4(o0, o1, o2, o3);
            p[1] = make_float4(o4, o5, o6, o7);
        }
    }
}

// ---------------- gather layer 1 (warp/node) + self + bias + relu -----------
__global__ __launch_bounds__(256) void k_gather1(const float *__restrict__ b1) {
    int w = (blockIdx.x * blockDim.x + threadIdx.x) >> 5;
    int lane = threadIdx.x & 31;
    if (w >= NN) return;
    float dw = g_dinv[w];
    int beg = g_off[w], n = g_cnt[w];

    float cs = dw * dw;                           // self-loop norm
    float4 acc = *reinterpret_cast<const float4 *>(&g_xw[(size_t)w * HID + lane * 4]);
    acc.x *= cs; acc.y *= cs; acc.z *= cs; acc.w *= cs;

    for (int j = 0; j < n; j++) {
        int s = __ldg(&g_csr[beg + j]);
        float c = __ldg(&g_dinv[s]) * dw;
        float4 v = *reinterpret_cast<const float4 *>(&g_xw[(size_t)s * HID + lane * 4]);
        acc.x = fmaf(v.x, c, acc.x);
        acc.y = fmaf(v.y, c, acc.y);
        acc.z = fmaf(v.z, c, acc.z);
        acc.w = fmaf(v.w, c, acc.w);
    }
    float4 b = reinterpret_cast<const float4 *>(b1)[lane];
    acc.x = fmaxf(acc.x + b.x, 0.f);
    acc.y = fmaxf(acc.y + b.y, 0.f);
    acc.z = fmaxf(acc.z + b.z, 0.f);
    acc.w = fmaxf(acc.w + b.w, 0.f);
    *reinterpret_cast<float4 *>(&g_h[(size_t)w * HID + lane * 4]) = acc;
}

// ---------------- GEMM2: g_hw = h[NN,128] @ W2[128,47] (padded 48) ----------
__global__ __launch_bounds__(256) void k_gemm2(const float *__restrict__ W2) {
    __shared__ float As[16][128];
    __shared__ float Bs[16][48];
    const int tid = threadIdx.x;
    const int m0  = blockIdx.x * 128;
    const int ty  = tid >> 3;
    const int tx  = tid & 7;

    ull acc[4][3];
#pragma unroll
    for (int i = 0; i < 4; i++)
#pragma unroll
        for (int j = 0; j < 3; j++) acc[i][j] = 0ull;

    for (int kt = 0; kt < HID; kt += 16) {
#pragma unroll
        for (int l = 0; l < 2; l++) {
            int q = tid + l * 256;
            int r = q >> 2, c4 = q & 3;
            int row = m0 + r;
            float4 v = make_float4(0.f, 0.f, 0.f, 0.f);
            if (row < NN)
                v = *reinterpret_cast<const float4 *>(&g_h[(size_t)row * HID + kt + c4 * 4]);
            As[c4 * 4 + 0][r] = v.x; As[c4 * 4 + 1][r] = v.y;
            As[c4 * 4 + 2][r] = v.z; As[c4 * 4 + 3][r] = v.w;
        }
#pragma unroll
        for (int l = 0; l < 3; l++) {
            int q = tid + l * 256;
            int k = q / 48, c = q % 48;
            Bs[k][c] = (c < NC) ? W2[(size_t)(kt + k) * NC + c] : 0.f;
        }
        __syncthreads();
#pragma unroll
        for (int kk = 0; kk < 16; kk++) {
            float4 a = *reinterpret_cast<float4 *>(&As[kk][ty * 4]);
            float2 c0 = *reinterpret_cast<float2 *>(&Bs[kk][tx * 6]);
            float2 c1 = *reinterpret_cast<float2 *>(&Bs[kk][tx * 6 + 2]);
            float2 c2 = *reinterpret_cast<float2 *>(&Bs[kk][tx * 6 + 4]);
            ull bb[3] = { pk2(c0.x, c0.y), pk2(c1.x, c1.y), pk2(c2.x, c2.y) };
            float av[4] = { a.x, a.y, a.z, a.w };
#pragma unroll
            for (int i = 0; i < 4; i++) {
                ull aa = pk2(av[i], av[i]);
#pragma unroll
                for (int jj = 0; jj < 3; jj++) acc[i][jj] = fma2(aa, bb[jj], acc[i][jj]);
            }
        }
        __syncthreads();
    }
#pragma unroll
    for (int i = 0; i < 4; i++) {
        int row = m0 + ty * 4 + i;
        if (row < NN) {
            float o0, o1, o2, o3, o4, o5;
            unpk2(acc[i][0], o0, o1); unpk2(acc[i][1], o2, o3); unpk2(acc[i][2], o4, o5);
            float *p = &g_hw[(size_t)row * NCP + tx * 6];
            *reinterpret_cast<float2 *>(p)     = make_float2(o0, o1);
            *reinterpret_cast<float2 *>(p + 2) = make_float2(o2, o3);
            *reinterpret_cast<float2 *>(p + 4) = make_float2(o4, o5);
        }
    }
}

// ---------------- gather layer 2 + bias + log_softmax -----------------------
__global__ __launch_bounds__(256) void k_gather2(const float *__restrict__ b2,
                                                 float *__restrict__ out) {
    int w = (blockIdx.x * blockDim.x + threadIdx.x) >> 5;
    int lane = threadIdx.x & 31;
    if (w >= NN) return;
    float dw = g_dinv[w];
    int beg = g_off[w], n = g_cnt[w];

    int grp = lane / 12;              // 0 or 1 active, 2 idle (lanes 24..31)
    int col = lane - grp * 12;        // 0..11 (float4 index)

    float4 acc = make_float4(0.f, 0.f, 0.f, 0.f);
    if (lane < 12) {                  // self loop into group 0
        float cs = dw * dw;
        float4 v = *reinterpret_cast<const float4 *>(&g_hw[(size_t)w * NCP + lane * 4]);
        acc = make_float4(v.x * cs, v.y * cs, v.z * cs, v.w * cs);
    }
    for (int j = 0; j < n; j += 2) {  // 2 edges per trip (groups 0,1)
        int e = j + grp;
        if (grp < 2 && e < n) {
            int s = __ldg(&g_csr[beg + e]);
            float c = __ldg(&g_dinv[s]) * dw;
            float4 v = *reinterpret_cast<const float4 *>(&g_hw[(size_t)s * NCP + col * 4]);
            acc.x = fmaf(v.x, c, acc.x);
            acc.y = fmaf(v.y, c, acc.y);
            acc.z = fmaf(v.z, c, acc.z);
            acc.w = fmaf(v.w, c, acc.w);
        }
    }
    // fold group1 into group0
    acc.x += __shfl_sync(0xffffffffu, acc.x, (lane + 12) & 31);
    acc.y += __shfl_sync(0xffffffffu, acc.y, (lane + 12) & 31);
    acc.z += __shfl_sync(0xffffffffu, acc.z, (lane + 12) & 31);
    acc.w += __shfl_sync(0xffffffffu, acc.w, (lane + 12) & 31);

    // bias + log_softmax over 47 valid columns (lane 11's .w is padding)
    float zx = 0.f, zy = 0.f, zz = 0.f, zw = 0.f;
    bool act = (lane < 12);
    bool hasw = (lane < 11);
    if (act) {
        int c0 = lane * 4;
        zx = acc.x + b2[c0];
        zy = acc.y + b2[c0 + 1];
        zz = acc.z + b2[c0 + 2];
        zw = hasw ? (acc.w + b2[c0 + 3]) : -1e30f;
    }
    float m = act ? fmaxf(fmaxf(zx, zy), fmaxf(zz, zw)) : -1e30f;
#pragma unroll
    for (int o = 16; o > 0; o >>= 1)
        m = fmaxf(m, __shfl_xor_sync(0xffffffffu, m, o));
    float s = 0.f;
    if (act) s = expf(zx - m) + expf(zy - m) + expf(zz - m) + (hasw ? expf(zw - m) : 0.f);
#pragma unroll
    for (int o = 16; o > 0; o >>= 1)
        s += __shfl_xor_sync(0xffffffffu, s, o);
    float ls = logf(s) + m;
    if (act) {
        float *p = &out[(size_t)w * NC + lane * 4];
        p[0] = zx - ls;
        p[1] = zy - ls;
        p[2] = zz - ls;
        if (hasw) p[3] = zw - ls;
    }
}

// ---------------- launch ----------------------------------------------------
extern "C" void kernel_launch(void *const *d_in, const int *in_sizes, int n_in,
                              void *d_out, int out_size) {
    const float *x  = (const float *)d_in[0];
    const int   *ei = (const int   *)d_in[1];
    const float *W1 = (const float *)d_in[2];
    const float *b1 = (const float *)d_in[3];
    const float *W2 = (const float *)d_in[4];
    const float *b2 = (const float *)d_in[5];
    float *out = (float *)d_out;

    const int E = in_sizes[1] / 2;
    const int *src = ei;
    const int *dst = ei + E;

    // CSR build (counting sort by dst)
    k_zero_cnt<<<NB, 256>>>();
    k_hist<<<(E + 255) / 256, 256>>>(dst, E);
    k_scan1<<<NB, 256>>>();
    k_scan2<<<1, 512>>>();
    k_scan3<<<NB, 256>>>();
    k_fill<<<(E + 255) / 256, 256>>>(src, dst, E);

    // layer 1
    k_gemm1<<<(NN + 127) / 128, 256>>>(x, W1);
    k_gather1<<<(NN * 32 + 255) / 256, 256>>>(b1);

    // layer 2
    k_gemm2<<<(NN + 127) / 128, 256>>>(W2);
    k_gather2<<<(NN * 32 + 255) / 256, 256>>>(b2, out);
}

// round 5
// speedup vs baseline: 1.6769x; 1.2913x over previous
#include <cuda_runtime.h>
#include <cuda_bf16.h>
#include <cstdint>

#define NN   100000
#define FIN  256
#define HID  128
#define NC   47
#define NCP  48
#define EMAX 2000000
#define NB   ((NN + 255) / 256)

// ---------------- scratch (device globals) ----------------------------------
__device__ float g_xw [(size_t)NN * HID];
__device__ float g_h  [(size_t)NN * HID];
__device__ float g_hw [(size_t)NN * NCP];
__device__ float g_dinv[NN];
__device__ int   g_cnt [NN];
__device__ int   g_off [NN];
__device__ int   g_cur [NN];
__device__ int   g_csr [EMAX];
__device__ int   g_bsum[512];
__device__ __nv_bfloat16 g_w1t_hi[HID * FIN];   // W1^T split-hi [n=128][k=256]
__device__ __nv_bfloat16 g_w1t_lo[HID * FIN];   // W1^T split-lo

typedef unsigned long long ull;

__device__ __forceinline__ ull pk2(float lo, float hi) {
    ull r; asm("mov.b64 %0,{%1,%2};" : "=l"(r) : "f"(lo), "f"(hi)); return r;
}
__device__ __forceinline__ void unpk2(ull v, float &lo, float &hi) {
    asm("mov.b64 {%0,%1},%2;" : "=f"(lo), "=f"(hi) : "l"(v));
}
__device__ __forceinline__ ull fma2(ull a, ull b, ull c) {
    ull d; asm("fma.rn.f32x2 %0,%1,%2,%3;" : "=l"(d) : "l"(a), "l"(b), "l"(c)); return d;
}
__device__ __forceinline__ void mma_bf16(float *c, const uint32_t *a, const uint32_t *b) {
    asm("mma.sync.aligned.m16n8k16.row.col.f32.bf16.bf16.f32 "
        "{%0,%1,%2,%3}, {%4,%5,%6,%7}, {%8,%9}, {%0,%1,%2,%3};"
        : "+f"(c[0]), "+f"(c[1]), "+f"(c[2]), "+f"(c[3])
        : "r"(a[0]), "r"(a[1]), "r"(a[2]), "r"(a[3]), "r"(b[0]), "r"(b[1]));
}
__device__ __forceinline__ uint32_t bf16x2_of(float f0, float f1) {
    __nv_bfloat162 h = __floats2bfloat162_rn(f0, f1);   // .x = f0 (low half)
    return *reinterpret_cast<uint32_t *>(&h);
}

// ---------------- CSR build --------------------------------------------------
__global__ void k_zero_cnt() {
    int i = blockIdx.x * blockDim.x + threadIdx.x;
    if (i < NN) g_cnt[i] = 0;
}
__global__ void k_hist(const int *__restrict__ dst, int E) {
    int i = blockIdx.x * blockDim.x + threadIdx.x;
    if (i < E) atomicAdd(&g_cnt[dst[i]], 1);
}
__global__ void k_scan1() {
    __shared__ int sh[256];
    int i = blockIdx.x * 256 + threadIdx.x;
    sh[threadIdx.x] = (i < NN) ? g_cnt[i] : 0;
    __syncthreads();
#pragma unroll
    for (int o = 128; o > 0; o >>= 1) {
        if (threadIdx.x < o) sh[threadIdx.x] += sh[threadIdx.x + o];
        __syncthreads();
    }
    if (threadIdx.x == 0) g_bsum[blockIdx.x] = sh[0];
}
__global__ void k_scan2() {
    __shared__ int sh[512];
    int t = threadIdx.x;
    int v = (t < NB) ? g_bsum[t] : 0;
    sh[t] = v;
    __syncthreads();
#pragma unroll
    for (int o = 1; o < 512; o <<= 1) {
        int u = (t >= o) ? sh[t - o] : 0;
        __syncthreads();
        sh[t] += u;
        __syncthreads();
    }
    if (t < NB) g_bsum[t] = sh[t] - v;
}
__global__ void k_scan3() {
    __shared__ int sh[256];
    int t = threadIdx.x;
    int i = blockIdx.x * 256 + t;
    int v = (i < NN) ? g_cnt[i] : 0;
    sh[t] = v;
    __syncthreads();
#pragma unroll
    for (int o = 1; o < 256; o <<= 1) {
        int u = (t >= o) ? sh[t - o] : 0;
        __syncthreads();
        sh[t] += u;
        __syncthreads();
    }
    if (i < NN) {
        int ex = g_bsum[blockIdx.x] + sh[t] - v;
        g_off[i] = ex;
        g_cur[i] = ex;
        g_dinv[i] = rsqrtf((float)(v + 1));
    }
}
__global__ void k_fill(const int *__restrict__ src, const int *__restrict__ dst, int E) {
    int i = blockIdx.x * blockDim.x + threadIdx.x;
    if (i < E) {
        int pos = atomicAdd(&g_cur[dst[i]], 1);
        g_csr[pos] = src[i];
    }
}

// ---------------- W1 prep: transpose + bf16 split ---------------------------
__global__ void k_w1prep(const float *__restrict__ W1) {
    int i = blockIdx.x * blockDim.x + threadIdx.x;
    if (i >= HID * FIN) return;
    int n = i >> 8;                 // output row (0..127)
    int k = i & 255;                // output col (0..255)
    float x = W1[(size_t)k * HID + n];
    __nv_bfloat16 h = __float2bfloat16(x);
    g_w1t_hi[i] = h;
    g_w1t_lo[i] = __float2bfloat16(x - __bfloat162float(h));
}

// ---------------- GEMM1 via mma.sync bf16 split (3 passes) ------------------
// Block tile 128x128, BK=64, 8 warps (4x2), warp tile 32x64 (2x8 m16n8k16 atoms)
#define APITCH 36      // 32-bit words per 64-bf16 row (+4 pad -> conflict-free)
#define ATILE  (128 * APITCH)
#define G1_SMEM (4 * ATILE * 4)     // 73728 bytes

__global__ __launch_bounds__(256, 1) void k_gemm1_mma(const float *__restrict__ X) {
    extern __shared__ uint32_t sm[];
    uint32_t *aHi = sm;
    uint32_t *aLo = sm + ATILE;
    uint32_t *bHi = sm + 2 * ATILE;
    uint32_t *bLo = sm + 3 * ATILE;

    const int tid  = threadIdx.x;
    const int wid  = tid >> 5, lane = tid & 31;
    const int g    = lane >> 2, tig = lane & 3;
    const int wM   = (wid & 3) * 32;     // warp row base
    const int wN   = (wid >> 2) * 64;    // warp col base
    const int m0   = blockIdx.x * 128;

    float acc[2][8][4];
#pragma unroll
    for (int i = 0; i < 2; i++)
#pragma unroll
        for (int j = 0; j < 8; j++)
#pragma unroll
            for (int l = 0; l < 4; l++) acc[i][j][l] = 0.f;

    for (int ch = 0; ch < 4; ch++) {                  // K chunks of 64
        // ---- fill A (inline f32 -> bf16 hi/lo split) ----
#pragma unroll
        for (int it = 0; it < 8; it++) {              // 2048 float4 / 256 thr
            int q = tid + it * 256;
            int row = q >> 4, c4 = q & 15;
            int grow = m0 + row;
            float4 v = make_float4(0.f, 0.f, 0.f, 0.f);
            if (grow < NN)
                v = *reinterpret_cast<const float4 *>(&X[(size_t)grow * FIN + ch * 64 + c4 * 4]);
            float hx = __bfloat162float(__float2bfloat16(v.x));
            float hy = __bfloat162float(__float2bfloat16(v.y));
            float hz = __bfloat162float(__float2bfloat16(v.z));
            float hw = __bfloat162float(__float2bfloat16(v.w));
            int o = row * APITCH + c4 * 2;
            aHi[o]     = bf16x2_of(hx, hy);
            aHi[o + 1] = bf16x2_of(hz, hw);
            aLo[o]     = bf16x2_of(v.x - hx, v.y - hy);
            aLo[o + 1] = bf16x2_of(v.z - hz, v.w - hw);
        }
        // ---- fill B (pre-split bf16, [n][k] layout): 128 rows x 8 uint4 ----
#pragma unroll
        for (int it = 0; it < 4; it++) {              // 1024 uint4 / 256 thr
            int q = tid + it * 256;
            int row = q >> 3, c4 = q & 7;             // row 0..127, c4 0..7
            size_t gi = (size_t)row * FIN + ch * 64 + c4 * 8;
            *reinterpret_cast<uint4 *>(&bHi[row * APITCH + c4 * 4]) =
                *reinterpret_cast<const uint4 *>(&g_w1t_hi[gi]);
            *reinterpret_cast<uint4 *>(&bLo[row * APITCH + c4 * 4]) =
                *reinterpret_cast<const uint4 *>(&g_w1t_lo[gi]);
        }
        __syncthreads();

#pragma unroll
        for (int k16 = 0; k16 < 4; k16++) {
            const int kw = k16 * 8;
            uint32_t Ah[2][4], Al[2][4], Bh[8][2], Bl[8][2];
#pragma unroll
            for (int ma = 0; ma < 2; ma++) {
                int r0 = (wM + ma * 16 + g) * APITCH + kw + tig;
                int r1 = (wM + ma * 16 + g + 8) * APITCH + kw + tig;
                Ah[ma][0] = aHi[r0]; Ah[ma][1] = aHi[r1];
                Ah[ma][2] = aHi[r0 + 4]; Ah[ma][3] = aHi[r1 + 4];
                Al[ma][0] = aLo[r0]; Al[ma][1] = aLo[r1];
                Al[ma][2] = aLo[r0 + 4]; Al[ma][3] = aLo[r1 + 4];
            }
#pragma unroll
            for (int na = 0; na < 8; na++) {
                int b0 = (wN + na * 8 + g) * APITCH + kw + tig;
                Bh[na][0] = bHi[b0]; Bh[na][1] = bHi[b0 + 4];
                Bl[na][0] = bLo[b0]; Bl[na][1] = bLo[b0 + 4];
            }
#pragma unroll
            for (int ma = 0; ma < 2; ma++)
#pragma unroll
                for (int na = 0; na < 8; na++) {
                    mma_bf16(acc[ma][na], Ah[ma], Bh[na]);
                    mma_bf16(acc[ma][na], Ah[ma], Bl[na]);
                    mma_bf16(acc[ma][na], Al[ma], Bh[na]);
                }
        }
        __syncthreads();
    }

    // ---- epilogue ----
#pragma unroll
    for (int ma = 0; ma < 2; ma++) {
        int row0 = m0 + wM + ma * 16 + g;
        int row1 = row0 + 8;
#pragma unroll
        for (int na = 0; na < 8; na++) {
            int col = wN + na * 8 + tig * 2;
            if (row0 < NN)
                *reinterpret_cast<float2 *>(&g_xw[(size_t)row0 * HID + col]) =
                    make_float2(acc[ma][na][0], acc[ma][na][1]);
            if (row1 < NN)
                *reinterpret_cast<float2 *>(&g_xw[(size_t)row1 * HID + col]) =
                    make_float2(acc[ma][na][2], acc[ma][na][3]);
        }
    }
}

// ---------------- gather layer 1 (warp/node) + self + bias + relu -----------
__global__ __launch_bounds__(256) void k_gather1(const float *__restrict__ b1) {
    int w = (blockIdx.x * blockDim.x + threadIdx.x) >> 5;
    int lane = threadIdx.x & 31;
    if (w >= NN) return;
    float dw = g_dinv[w];
    int beg = g_off[w], n = g_cnt[w];

    float cs = dw * dw;
    float4 a0 = *reinterpret_cast<const float4 *>(&g_xw[(size_t)w * HID + lane * 4]);
    a0.x *= cs; a0.y *= cs; a0.z *= cs; a0.w *= cs;
    float4 a1 = make_float4(0.f, 0.f, 0.f, 0.f);

    int j = 0;
    for (; j + 2 <= n; j += 2) {
        int s0 = __ldg(&g_csr[beg + j]);
        int s1 = __ldg(&g_csr[beg + j + 1]);
        float c0 = __ldg(&g_dinv[s0]) * dw;
        float c1 = __ldg(&g_dinv[s1]) * dw;
        float4 v0 = *reinterpret_cast<const float4 *>(&g_xw[(size_t)s0 * HID + lane * 4]);
        float4 v1 = *reinterpret_cast<const float4 *>(&g_xw[(size_t)s1 * HID + lane * 4]);
        a0.x = fmaf(v0.x, c0, a0.x); a0.y = fmaf(v0.y, c0, a0.y);
        a0.z = fmaf(v0.z, c0, a0.z); a0.w = fmaf(v0.w, c0, a0.w);
        a1.x = fmaf(v1.x, c1, a1.x); a1.y = fmaf(v1.y, c1, a1.y);
        a1.z = fmaf(v1.z, c1, a1.z); a1.w = fmaf(v1.w, c1, a1.w);
    }
    if (j < n) {
        int s0 = __ldg(&g_csr[beg + j]);
        float c0 = __ldg(&g_dinv[s0]) * dw;
        float4 v0 = *reinterpret_cast<const float4 *>(&g_xw[(size_t)s0 * HID + lane * 4]);
        a0.x = fmaf(v0.x, c0, a0.x); a0.y = fmaf(v0.y, c0, a0.y);
        a0.z = fmaf(v0.z, c0, a0.z); a0.w = fmaf(v0.w, c0, a0.w);
    }
    float4 b = reinterpret_cast<const float4 *>(b1)[lane];
    float4 r;
    r.x = fmaxf(a0.x + a1.x + b.x, 0.f);
    r.y = fmaxf(a0.y + a1.y + b.y, 0.f);
    r.z = fmaxf(a0.z + a1.z + b.z, 0.f);
    r.w = fmaxf(a0.w + a1.w + b.w, 0.f);
    *reinterpret_cast<float4 *>(&g_h[(size_t)w * HID + lane * 4]) = r;
}

// ---------------- GEMM2: g_hw = h[NN,128] @ W2[128,47] (padded 48) ----------
__global__ __launch_bounds__(256) void k_gemm2(const float *__restrict__ W2) {
    __shared__ float As[16][128];
    __shared__ float Bs[16][48];
    const int tid = threadIdx.x;
    const int m0  = blockIdx.x * 128;
    const int ty  = tid >> 3;
    const int tx  = tid & 7;

    ull acc[4][3];
#pragma unroll
    for (int i = 0; i < 4; i++)
#pragma unroll
        for (int j = 0; j < 3; j++) acc[i][j] = 0ull;

    for (int kt = 0; kt < HID; kt += 16) {
#pragma unroll
        for (int l = 0; l < 2; l++) {
            int q = tid + l * 256;
            int r = q >> 2, c4 = q & 3;
            int row = m0 + r;
            float4 v = make_float4(0.f, 0.f, 0.f, 0.f);
            if (row < NN)
                v = *reinterpret_cast<const float4 *>(&g_h[(size_t)row * HID + kt + c4 * 4]);
            As[c4 * 4 + 0][r] = v.x; As[c4 * 4 + 1][r] = v.y;
            As[c4 * 4 + 2][r] = v.z; As[c4 * 4 + 3][r] = v.w;
        }
#pragma unroll
        for (int l = 0; l < 3; l++) {
            int q = tid + l * 256;
            int k = q / 48, c = q % 48;
            Bs[k][c] = (c < NC) ? W2[(size_t)(kt + k) * NC + c] : 0.f;
        }
        __syncthreads();
#pragma unroll
        for (int kk = 0; kk < 16; kk++) {
            float4 a = *reinterpret_cast<float4 *>(&As[kk][ty * 4]);
            float2 c0 = *reinterpret_cast<float2 *>(&Bs[kk][tx * 6]);
            float2 c1 = *reinterpret_cast<float2 *>(&Bs[kk][tx * 6 + 2]);
            float2 c2 = *reinterpret_cast<float2 *>(&Bs[kk][tx * 6 + 4]);
            ull bb[3] = { pk2(c0.x, c0.y), pk2(c1.x, c1.y), pk2(c2.x, c2.y) };
            float av[4] = { a.x, a.y, a.z, a.w };
#pragma unroll
            for (int i = 0; i < 4; i++) {
                ull aa = pk2(av[i], av[i]);
#pragma unroll
                for (int jj = 0; jj < 3; jj++) acc[i][jj] = fma2(aa, bb[jj], acc[i][jj]);
            }
        }
        __syncthreads();
    }
#pragma unroll
    for (int i = 0; i < 4; i++) {
        int row = m0 + ty * 4 + i;
        if (row < NN) {
            float o0, o1, o2, o3, o4, o5;
            unpk2(acc[i][0], o0, o1); unpk2(acc[i][1], o2, o3); unpk2(acc[i][2], o4, o5);
            float *p = &g_hw[(size_t)row * NCP + tx * 6];
            *reinterpret_cast<float2 *>(p)     = make_float2(o0, o1);
            *reinterpret_cast<float2 *>(p + 2) = make_float2(o2, o3);
            *reinterpret_cast<float2 *>(p + 4) = make_float2(o4, o5);
        }
    }
}

// ---------------- gather layer 2 + bias + log_softmax -----------------------
__global__ __launch_bounds__(256) void k_gather2(const float *__restrict__ b2,
                                                 float *__restrict__ out) {
    int w = (blockIdx.x * blockDim.x + threadIdx.x) >> 5;
    int lane = threadIdx.x & 31;
    if (w >= NN) return;
    float dw = g_dinv[w];
    int beg = g_off[w], n = g_cnt[w];

    int grp = lane / 12;
    int col = lane - grp * 12;

    float4 acc = make_float4(0.f, 0.f, 0.f, 0.f);
    if (lane < 12) {
        float cs = dw * dw;
        float4 v = *reinterpret_cast<const float4 *>(&g_hw[(size_t)w * NCP + lane * 4]);
        acc = make_float4(v.x * cs, v.y * cs, v.z * cs, v.w * cs);
    }
    for (int j = 0; j < n; j += 2) {
        int e = j + grp;
        if (grp < 2 && e < n) {
            int s = __ldg(&g_csr[beg + e]);
            float c = __ldg(&g_dinv[s]) * dw;
            float4 v = *reinterpret_cast<const float4 *>(&g_hw[(size_t)s * NCP + col * 4]);
            acc.x = fmaf(v.x, c, acc.x);
            acc.y = fmaf(v.y, c, acc.y);
            acc.z = fmaf(v.z, c, acc.z);
            acc.w = fmaf(v.w, c, acc.w);
        }
    }
    acc.x += __shfl_sync(0xffffffffu, acc.x, (lane + 12) & 31);
    acc.y += __shfl_sync(0xffffffffu, acc.y, (lane + 12) & 31);
    acc.z += __shfl_sync(0xffffffffu, acc.z, (lane + 12) & 31);
    acc.w += __shfl_sync(0xffffffffu, acc.w, (lane + 12) & 31);

    float zx = 0.f, zy = 0.f, zz = 0.f, zw = 0.f;
    bool act = (lane < 12);
    bool hasw = (lane < 11);
    if (act) {
        int c0 = lane * 4;
        zx = acc.x + b2[c0];
        zy = acc.y + b2[c0 + 1];
        zz = acc.z + b2[c0 + 2];
        zw = hasw ? (acc.w + b2[c0 + 3]) : -1e30f;
    }
    float m = act ? fmaxf(fmaxf(zx, zy), fmaxf(zz, zw)) : -1e30f;
#pragma unroll
    for (int o = 16; o > 0; o >>= 1)
        m = fmaxf(m, __shfl_xor_sync(0xffffffffu, m, o));
    float s = 0.f;
    if (act) s = expf(zx - m) + expf(zy - m) + expf(zz - m) + (hasw ? expf(zw - m) : 0.f);
#pragma unroll
    for (int o = 16; o > 0; o >>= 1)
        s += __shfl_xor_sync(0xffffffffu, s, o);
    float ls = logf(s) + m;
    if (act) {
        float *p = &out[(size_t)w * NC + lane * 4];
        p[0] = zx - ls;
        p[1] = zy - ls;
        p[2] = zz - ls;
        if (hasw) p[3] = zw - ls;
    }
}

// ---------------- launch ----------------------------------------------------
extern "C" void kernel_launch(void *const *d_in, const int *in_sizes, int n_in,
                              void *d_out, int out_size) {
    const float *x  = (const float *)d_in[0];
    const int   *ei = (const int   *)d_in[1];
    const float *W1 = (const float *)d_in[2];
    const float *b1 = (const float *)d_in[3];
    const float *W2 = (const float *)d_in[4];
    const float *b2 = (const float *)d_in[5];
    float *out = (float *)d_out;

    const int E = in_sizes[1] / 2;
    const int *src = ei;
    const int *dst = ei + E;

    cudaFuncSetAttribute(k_gemm1_mma, cudaFuncAttributeMaxDynamicSharedMemorySize, G1_SMEM);

    k_zero_cnt<<<NB, 256>>>();                                   // 1
    k_hist<<<(E + 255) / 256, 256>>>(dst, E);                    // 2
    k_w1prep<<<(HID * FIN + 255) / 256, 256>>>(W1);              // 3
    k_gemm1_mma<<<(NN + 127) / 128, 256, G1_SMEM>>>(x);          // 4 <- profiled
    k_scan1<<<NB, 256>>>();                                      // 5
    k_scan2<<<1, 512>>>();                                       // 6
    k_scan3<<<NB, 256>>>();                                      // 7
    k_fill<<<(E + 255) / 256, 256>>>(src, dst, E);               // 8
    k_gather1<<<(NN * 32 + 255) / 256, 256>>>(b1);               // 9
    k_gemm2<<<(NN + 127) / 128, 256>>>(W2);                      // 10
    k_gather2<<<(NN * 32 + 255) / 256, 256>>>(b2, out);          // 11
}

// round 6
// speedup vs baseline: 1.6969x; 1.0119x over previous
#include <cuda_runtime.h>
#include <cuda_bf16.h>
#include <cstdint>

#define NN   100000
#define FIN  256
#define HID  128
#define NC   47
#define NCP  48
#define EMAX 2000000
#define NB   ((NN + 255) / 256)

// ---------------- scratch (device globals) ----------------------------------
__device__ float g_xw [(size_t)NN * HID];
__device__ float g_h  [(size_t)NN * HID];
__device__ float g_hw [(size_t)NN * NCP];
__device__ float g_dinv[NN];
__device__ int   g_cnt [NN];
__device__ int   g_off [NN];
__device__ int   g_cur [NN];
__device__ int   g_csr [EMAX];
__device__ int   g_bsum[512];
__device__ __nv_bfloat16 g_w1t_hi[HID * FIN];   // W1^T split-hi [n=128][k=256]
__device__ __nv_bfloat16 g_w1t_lo[HID * FIN];   // W1^T split-lo

typedef unsigned long long ull;

__device__ __forceinline__ ull pk2(float lo, float hi) {
    ull r; asm("mov.b64 %0,{%1,%2};" : "=l"(r) : "f"(lo), "f"(hi)); return r;
}
__device__ __forceinline__ void unpk2(ull v, float &lo, float &hi) {
    asm("mov.b64 {%0,%1},%2;" : "=f"(lo), "=f"(hi) : "l"(v));
}
__device__ __forceinline__ ull fma2(ull a, ull b, ull c) {
    ull d; asm("fma.rn.f32x2 %0,%1,%2,%3;" : "=l"(d) : "l"(a), "l"(b), "l"(c)); return d;
}
__device__ __forceinline__ void mma_bf16(float *c, const uint32_t *a, const uint32_t *b) {
    asm("mma.sync.aligned.m16n8k16.row.col.f32.bf16.bf16.f32 "
        "{%0,%1,%2,%3}, {%4,%5,%6,%7}, {%8,%9}, {%0,%1,%2,%3};"
        : "+f"(c[0]), "+f"(c[1]), "+f"(c[2]), "+f"(c[3])
        : "r"(a[0]), "r"(a[1]), "r"(a[2]), "r"(a[3]), "r"(b[0]), "r"(b[1]));
}
__device__ __forceinline__ uint32_t bf16x2_of(float f0, float f1) {
    __nv_bfloat162 h = __floats2bfloat162_rn(f0, f1);
    return *reinterpret_cast<uint32_t *>(&h);
}

// ---------------- CSR build --------------------------------------------------
__global__ void k_zero_cnt() {
    int i = blockIdx.x * blockDim.x + threadIdx.x;
    if (i < NN) g_cnt[i] = 0;
}
__global__ void k_hist(const int *__restrict__ dst, int E) {
    int i = blockIdx.x * blockDim.x + threadIdx.x;
    if (i < E) atomicAdd(&g_cnt[dst[i]], 1);
}
__global__ void k_scan1() {
    __shared__ int sh[256];
    int i = blockIdx.x * 256 + threadIdx.x;
    sh[threadIdx.x] = (i < NN) ? g_cnt[i] : 0;
    __syncthreads();
#pragma unroll
    for (int o = 128; o > 0; o >>= 1) {
        if (threadIdx.x < o) sh[threadIdx.x] += sh[threadIdx.x + o];
        __syncthreads();
    }
    if (threadIdx.x == 0) g_bsum[blockIdx.x] = sh[0];
}
__global__ void k_scan2() {
    __shared__ int sh[512];
    int t = threadIdx.x;
    int v = (t < NB) ? g_bsum[t] : 0;
    sh[t] = v;
    __syncthreads();
#pragma unroll
    for (int o = 1; o < 512; o <<= 1) {
        int u = (t >= o) ? sh[t - o] : 0;
        __syncthreads();
        sh[t] += u;
        __syncthreads();
    }
    if (t < NB) g_bsum[t] = sh[t] - v;
}
__global__ void k_scan3() {
    __shared__ int sh[256];
    int t = threadIdx.x;
    int i = blockIdx.x * 256 + t;
    int v = (i < NN) ? g_cnt[i] : 0;
    sh[t] = v;
    __syncthreads();
#pragma unroll
    for (int o = 1; o < 256; o <<= 1) {
        int u = (t >= o) ? sh[t - o] : 0;
        __syncthreads();
        sh[t] += u;
        __syncthreads();
    }
    if (i < NN) {
        int ex = g_bsum[blockIdx.x] + sh[t] - v;
        g_off[i] = ex;
        g_cur[i] = ex;
        g_dinv[i] = rsqrtf((float)(v + 1));
    }
}
__global__ void k_fill(const int *__restrict__ src, const int *__restrict__ dst, int E) {
    int i = blockIdx.x * blockDim.x + threadIdx.x;
    if (i < E) {
        int pos = atomicAdd(&g_cur[dst[i]], 1);
        g_csr[pos] = src[i];
    }
}

// ---------------- W1 prep: transpose + bf16 split ---------------------------
__global__ void k_w1prep(const float *__restrict__ W1) {
    int i = blockIdx.x * blockDim.x + threadIdx.x;
    if (i >= HID * FIN) return;
    int n = i >> 8;
    int k = i & 255;
    float x = W1[(size_t)k * HID + n];
    __nv_bfloat16 h = __float2bfloat16(x);
    g_w1t_hi[i] = h;
    g_w1t_lo[i] = __float2bfloat16(x - __bfloat162float(h));
}

// ---------------- GEMM1: bf16-split 3-pass, B smem-resident, A pipelined ----
// Block 128x128, BK=32 (8 chunks), 8 warps (4x2), warp tile 32x64.
#define BPITCH 132                       // words per B row (128 + 4 pad)
#define APITCH2 20                       // words per A row (16 + 4 pad)
#define B_WORDS (128 * BPITCH)           // 16896 per hi/lo
#define A_WORDS (128 * APITCH2)          // 2560 per tile
#define G1_SMEM ((2 * B_WORDS + 4 * A_WORDS) * 4)   // 176128 bytes

__global__ __launch_bounds__(256, 1) void k_gemm1_mma(const float *__restrict__ X) {
    extern __shared__ uint32_t sm[];
    uint32_t *bHi = sm;
    uint32_t *bLo = sm + B_WORDS;
    uint32_t *aBuf = sm + 2 * B_WORDS;   // [s][hi|lo] each A_WORDS

    const int tid  = threadIdx.x;
    const int wid  = tid >> 5, lane = tid & 31;
    const int g    = lane >> 2, tig = lane & 3;
    const int wM   = (wid & 3) * 32;
    const int wN   = (wid >> 2) * 64;
    const int m0   = blockIdx.x * 128;

    // ---- load whole B (hi/lo) into smem: 4096 uint4 each ----
#pragma unroll
    for (int it = 0; it < 16; it++) {
        int q = tid + it * 256;
        int row = q >> 5, c4 = q & 31;           // 32 uint4 per 256-bf16 row
        size_t gi = (size_t)row * FIN + c4 * 8;
        *reinterpret_cast<uint4 *>(&bHi[row * BPITCH + c4 * 4]) =
            *reinterpret_cast<const uint4 *>(&g_w1t_hi[gi]);
        *reinterpret_cast<uint4 *>(&bLo[row * BPITCH + c4 * 4]) =
            *reinterpret_cast<const uint4 *>(&g_w1t_lo[gi]);
    }

    float acc[2][8][4];
#pragma unroll
    for (int i = 0; i < 2; i++)
#pragma unroll
        for (int j = 0; j < 8; j++)
#pragma unroll
            for (int l = 0; l < 4; l++) acc[i][j][l] = 0.f;

    // ---- A stage: each thread owns 4 float4 slots of a 128x32 chunk ----
    // slot q: row = q>>3 (0..127), c4 = q&7 (8 float4 per 32-f32 row)
    float4 stg[4];
    const int srow = tid >> 1;                   // rows: tid/2*? -- recompute per it
    (void)srow;

#pragma unroll
    for (int it = 0; it < 4; it++) {             // prologue: LDG chunk 0
        int q = tid + it * 256;
        int row = q >> 3, c4 = q & 7;
        int grow = m0 + row;
        stg[it] = make_float4(0.f, 0.f, 0.f, 0.f);
        if (grow < NN)
            stg[it] = *reinterpret_cast<const float4 *>(&X[(size_t)grow * FIN + c4 * 4]);
    }
    // convert + store chunk 0 into buffer 0
    {
        uint32_t *aHi = aBuf, *aLo = aBuf + A_WORDS;
#pragma unroll
        for (int it = 0; it < 4; it++) {
            int q = tid + it * 256;
            int row = q >> 3, c4 = q & 7;
            float4 v = stg[it];
            float hx = __bfloat162float(__float2bfloat16(v.x));
            float hy = __bfloat162float(__float2bfloat16(v.y));
            float hz = __bfloat162float(__float2bfloat16(v.z));
            float hw = __bfloat162float(__float2bfloat16(v.w));
            int o = row * APITCH2 + c4 * 2;
            aHi[o]     = bf16x2_of(hx, hy);
            aHi[o + 1] = bf16x2_of(hz, hw);
            aLo[o]     = bf16x2_of(v.x - hx, v.y - hy);
            aLo[o + 1] = bf16x2_of(v.z - hz, v.w - hw);
        }
    }
    __syncthreads();

    for (int ch = 0; ch < 8; ch++) {             // 8 K-chunks of 32
        // ---- prefetch next chunk to registers (overlaps with MMA below) ----
        if (ch < 7) {
#pragma unroll
            for (int it = 0; it < 4; it++) {
                int q = tid + it * 256;
                int row = q >> 3, c4 = q & 7;
                int grow = m0 + row;
                stg[it] = make_float4(0.f, 0.f, 0.f, 0.f);
                if (grow < NN)
                    stg[it] = *reinterpret_cast<const float4 *>(
                        &X[(size_t)grow * FIN + (ch + 1) * 32 + c4 * 4]);
            }
        }

        // ---- MMA on current buffer ----
        uint32_t *aHi = aBuf + (ch & 1) * 2 * A_WORDS;
        uint32_t *aLo = aHi + A_WORDS;
#pragma unroll
        for (int k16 = 0; k16 < 2; k16++) {
            const int kw = k16 * 8;
            uint32_t Ah[2][4], Al[2][4], Bh[8][2], Bl[8][2];
#pragma unroll
            for (int ma = 0; ma < 2; ma++) {
                int r0 = (wM + ma * 16 + g) * APITCH2 + kw + tig;
                int r1 = r0 + 8 * APITCH2;
                Ah[ma][0] = aHi[r0]; Ah[ma][1] = aHi[r1];
                Ah[ma][2] = aHi[r0 + 4]; Ah[ma][3] = aHi[r1 + 4];
                Al[ma][0] = aLo[r0]; Al[ma][1] = aLo[r1];
                Al[ma][2] = aLo[r0 + 4]; Al[ma][3] = aLo[r1 + 4];
            }
#pragma unroll
            for (int na = 0; na < 8; na++) {
                int b0 = (wN + na * 8 + g) * BPITCH + ch * 16 + kw + tig;
                Bh[na][0] = bHi[b0]; Bh[na][1] = bHi[b0 + 4];
                Bl[na][0] = bLo[b0]; Bl[na][1] = bLo[b0 + 4];
            }
#pragma unroll
            for (int ma = 0; ma < 2; ma++)
#pragma unroll
                for (int na = 0; na < 8; na++) {
                    mma_bf16(acc[ma][na], Ah[ma], Bh[na]);
                    mma_bf16(acc[ma][na], Ah[ma], Bl[na]);
                    mma_bf16(acc[ma][na], Al[ma], Bh[na]);
                }
        }

        // ---- convert + store next chunk into the other buffer ----
        if (ch < 7) {
            uint32_t *nHi = aBuf + ((ch + 1) & 1) * 2 * A_WORDS;
            uint32_t *nLo = nHi + A_WORDS;
#pragma unroll
            for (int it = 0; it < 4; it++) {
                int q = tid + it * 256;
                int row = q >> 3, c4 = q & 7;
                float4 v = stg[it];
                float hx = __bfloat162float(__float2bfloat16(v.x));
                float hy = __bfloat162float(__float2bfloat16(v.y));
                float hz = __bfloat162float(__float2bfloat16(v.z));
                float hw = __bfloat162float(__float2bfloat16(v.w));
                int o = row * APITCH2 + c4 * 2;
                nHi[o]     = bf16x2_of(hx, hy);
                nHi[o + 1] = bf16x2_of(hz, hw);
                nLo[o]     = bf16x2_of(v.x - hx, v.y - hy);
                nLo[o + 1] = bf16x2_of(v.z - hz, v.w - hw);
            }
            __syncthreads();
        }
    }

    // ---- epilogue ----
#pragma unroll
    for (int ma = 0; ma < 2; ma++) {
        int row0 = m0 + wM + ma * 16 + g;
        int row1 = row0 + 8;
#pragma unroll
        for (int na = 0; na < 8; na++) {
            int col = wN + na * 8 + tig * 2;
            if (row0 < NN)
                *reinterpret_cast<float2 *>(&g_xw[(size_t)row0 * HID + col]) =
                    make_float2(acc[ma][na][0], acc[ma][na][1]);
            if (row1 < NN)
                *reinterpret_cast<float2 *>(&g_xw[(size_t)row1 * HID + col]) =
                    make_float2(acc[ma][na][2], acc[ma][na][3]);
        }
    }
}

// ---------------- gather layer 1 (warp/node) + self + bias + relu -----------
__global__ __launch_bounds__(256) void k_gather1(const float *__restrict__ b1) {
    int w = (blockIdx.x * blockDim.x + threadIdx.x) >> 5;
    int lane = threadIdx.x & 31;
    if (w >= NN) return;
    float dw = g_dinv[w];
    int beg = g_off[w], n = g_cnt[w];

    float cs = dw * dw;
    float4 a0 = *reinterpret_cast<const float4 *>(&g_xw[(size_t)w * HID + lane * 4]);
    a0.x *= cs; a0.y *= cs; a0.z *= cs; a0.w *= cs;
    float4 a1 = make_float4(0.f, 0.f, 0.f, 0.f);

    int j = 0;
    for (; j + 2 <= n; j += 2) {
        int s0 = __ldg(&g_csr[beg + j]);
        int s1 = __ldg(&g_csr[beg + j + 1]);
        float c0 = __ldg(&g_dinv[s0]) * dw;
        float c1 = __ldg(&g_dinv[s1]) * dw;
        float4 v0 = *reinterpret_cast<const float4 *>(&g_xw[(size_t)s0 * HID + lane * 4]);
        float4 v1 = *reinterpret_cast<const float4 *>(&g_xw[(size_t)s1 * HID + lane * 4]);
        a0.x = fmaf(v0.x, c0, a0.x); a0.y = fmaf(v0.y, c0, a0.y);
        a0.z = fmaf(v0.z, c0, a0.z); a0.w = fmaf(v0.w, c0, a0.w);
        a1.x = fmaf(v1.x, c1, a1.x); a1.y = fmaf(v1.y, c1, a1.y);
        a1.z = fmaf(v1.z, c1, a1.z); a1.w = fmaf(v1.w, c1, a1.w);
    }
    if (j < n) {
        int s0 = __ldg(&g_csr[beg + j]);
        float c0 = __ldg(&g_dinv[s0]) * dw;
        float4 v0 = *reinterpret_cast<const float4 *>(&g_xw[(size_t)s0 * HID + lane * 4]);
        a0.x = fmaf(v0.x, c0, a0.x); a0.y = fmaf(v0.y, c0, a0.y);
        a0.z = fmaf(v0.z, c0, a0.z); a0.w = fmaf(v0.w, c0, a0.w);
    }
    float4 b = reinterpret_cast<const float4 *>(b1)[lane];
    float4 r;
    r.x = fmaxf(a0.x + a1.x + b.x, 0.f);
    r.y = fmaxf(a0.y + a1.y + b.y, 0.f);
    r.z = fmaxf(a0.z + a1.z + b.z, 0.f);
    r.w = fmaxf(a0.w + a1.w + b.w, 0.f);
    *reinterpret_cast<float4 *>(&g_h[(size_t)w * HID + lane * 4]) = r;
}

// ---------------- GEMM2: g_hw = h[NN,128] @ W2[128,47] (padded 48) ----------
__global__ __launch_bounds__(256) void k_gemm2(const float *__restrict__ W2) {
    __shared__ float As[16][128];
    __shared__ float Bs[16][48];
    const int tid = threadIdx.x;
    const int m0  = blockIdx.x * 128;
    const int ty  = tid >> 3;
    const int tx  = tid & 7;

    ull acc[4][3];
#pragma unroll
    for (int i = 0; i < 4; i++)
#pragma unroll
        for (int j = 0; j < 3; j++) acc[i][j] = 0ull;

    for (int kt = 0; kt < HID; kt += 16) {
#pragma unroll
        for (int l = 0; l < 2; l++) {
            int q = tid + l * 256;
            int r = q >> 2, c4 = q & 3;
            int row = m0 + r;
            float4 v = make_float4(0.f, 0.f, 0.f, 0.f);
            if (row < NN)
                v = *reinterpret_cast<const float4 *>(&g_h[(size_t)row * HID + kt + c4 * 4]);
            As[c4 * 4 + 0][r] = v.x; As[c4 * 4 + 1][r] = v.y;
            As[c4 * 4 + 2][r] = v.z; As[c4 * 4 + 3][r] = v.w;
        }
#pragma unroll
        for (int l = 0; l < 3; l++) {
            int q = tid + l * 256;
            int k = q / 48, c = q % 48;
            Bs[k][c] = (c < NC) ? W2[(size_t)(kt + k) * NC + c] : 0.f;
        }
        __syncthreads();
#pragma unroll
        for (int kk = 0; kk < 16; kk++) {
            float4 a = *reinterpret_cast<float4 *>(&As[kk][ty * 4]);
            float2 c0 = *reinterpret_cast<float2 *>(&Bs[kk][tx * 6]);
            float2 c1 = *reinterpret_cast<float2 *>(&Bs[kk][tx * 6 + 2]);
            float2 c2 = *reinterpret_cast<float2 *>(&Bs[kk][tx * 6 + 4]);
            ull bb[3] = { pk2(c0.x, c0.y), pk2(c1.x, c1.y), pk2(c2.x, c2.y) };
            float av[4] = { a.x, a.y, a.z, a.w };
#pragma unroll
            for (int i = 0; i < 4; i++) {
                ull aa = pk2(av[i], av[i]);
#pragma unroll
                for (int jj = 0; jj < 3; jj++) acc[i][jj] = fma2(aa, bb[jj], acc[i][jj]);
            }
        }
        __syncthreads();
    }
#pragma unroll
    for (int i = 0; i < 4; i++) {
        int row = m0 + ty * 4 + i;
        if (row < NN) {
            float o0, o1, o2, o3, o4, o5;
            unpk2(acc[i][0], o0, o1); unpk2(acc[i][1], o2, o3); unpk2(acc[i][2], o4, o5);
            float *p = &g_hw[(size_t)row * NCP + tx * 6];
            *reinterpret_cast<float2 *>(p)     = make_float2(o0, o1);
            *reinterpret_cast<float2 *>(p + 2) = make_float2(o2, o3);
            *reinterpret_cast<float2 *>(p + 4) = make_float2(o4, o5);
        }
    }
}

// ---------------- gather layer 2 + bias + log_softmax -----------------------
__global__ __launch_bounds__(256) void k_gather2(const float *__restrict__ b2,
                                                 float *__restrict__ out) {
    int w = (blockIdx.x * blockDim.x + threadIdx.x) >> 5;
    int lane = threadIdx.x & 31;
    if (w >= NN) return;
    float dw = g_dinv[w];
    int beg = g_off[w], n = g_cnt[w];

    int grp = lane / 12;
    int col = lane - grp * 12;

    float4 acc = make_float4(0.f, 0.f, 0.f, 0.f);
    if (lane < 12) {
        float cs = dw * dw;
        float4 v = *reinterpret_cast<const float4 *>(&g_hw[(size_t)w * NCP + lane * 4]);
        acc = make_float4(v.x * cs, v.y * cs, v.z * cs, v.w * cs);
    }
    for (int j = 0; j < n; j += 2) {
        int e = j + grp;
        if (grp < 2 && e < n) {
            int s = __ldg(&g_csr[beg + e]);
            float c = __ldg(&g_dinv[s]) * dw;
            float4 v = *reinterpret_cast<const float4 *>(&g_hw[(size_t)s * NCP + col * 4]);
            acc.x = fmaf(v.x, c, acc.x);
            acc.y = fmaf(v.y, c, acc.y);
            acc.z = fmaf(v.z, c, acc.z);
            acc.w = fmaf(v.w, c, acc.w);
        }
    }
    acc.x += __shfl_sync(0xffffffffu, acc.x, (lane + 12) & 31);
    acc.y += __shfl_sync(0xffffffffu, acc.y, (lane + 12) & 31);
    acc.z += __shfl_sync(0xffffffffu, acc.z, (lane + 12) & 31);
    acc.w += __shfl_sync(0xffffffffu, acc.w, (lane + 12) & 31);

    float zx = 0.f, zy = 0.f, zz = 0.f, zw = 0.f;
    bool act = (lane < 12);
    bool hasw = (lane < 11);
    if (act) {
        int c0 = lane * 4;
        zx = acc.x + b2[c0];
        zy = acc.y + b2[c0 + 1];
        zz = acc.z + b2[c0 + 2];
        zw = hasw ? (acc.w + b2[c0 + 3]) : -1e30f;
    }
    float m = act ? fmaxf(fmaxf(zx, zy), fmaxf(zz, zw)) : -1e30f;
#pragma unroll
    for (int o = 16; o > 0; o >>= 1)
        m = fmaxf(m, __shfl_xor_sync(0xffffffffu, m, o));
    float s = 0.f;
    if (act) s = expf(zx - m) + expf(zy - m) + expf(zz - m) + (hasw ? expf(zw - m) : 0.f);
#pragma unroll
    for (int o = 16; o > 0; o >>= 1)
        s += __shfl_xor_sync(0xffffffffu, s, o);
    float ls = logf(s) + m;
    if (act) {
        float *p = &out[(size_t)w * NC + lane * 4];
        p[0] = zx - ls;
        p[1] = zy - ls;
        p[2] = zz - ls;
        if (hasw) p[3] = zw - ls;
    }
}

// ---------------- launch ----------------------------------------------------
extern "C" void kernel_launch(void *const *d_in, const int *in_sizes, int n_in,
                              void *d_out, int out_size) {
    const float *x  = (const float *)d_in[0];
    const int   *ei = (const int   *)d_in[1];
    const float *W1 = (const float *)d_in[2];
    const float *b1 = (const float *)d_in[3];
    const float *W2 = (const float *)d_in[4];
    const float *b2 = (const float *)d_in[5];
    float *out = (float *)d_out;

    const int E = in_sizes[1] / 2;
    const int *src = ei;
    const int *dst = ei + E;

    cudaFuncSetAttribute(k_gemm1_mma, cudaFuncAttributeMaxDynamicSharedMemorySize, G1_SMEM);

    k_zero_cnt<<<NB, 256>>>();                                   // 1
    k_hist<<<(E + 255) / 256, 256>>>(dst, E);                    // 2
    k_w1prep<<<(HID * FIN + 255) / 256, 256>>>(W1);              // 3
    k_gemm1_mma<<<(NN + 127) / 128, 256, G1_SMEM>>>(x);          // 4 <- profiled
    k_scan1<<<NB, 256>>>();                                      // 5
    k_scan2<<<1, 512>>>();                                       // 6
    k_scan3<<<NB, 256>>>();                                      // 7
    k_fill<<<(E + 255) / 256, 256>>>(src, dst, E);               // 8
    k_gather1<<<(NN * 32 + 255) / 256, 256>>>(b1);               // 9
    k_gemm2<<<(NN + 127) / 128, 256>>>(W2);                      // 10
    k_gather2<<<(NN * 32 + 255) / 256, 256>>>(b2, out);          // 11
}

// round 7
// speedup vs baseline: 1.7094x; 1.0073x over previous
#include <cuda_runtime.h>
#include <cuda_bf16.h>
#include <cstdint>

#define NN   100000
#define FIN  256
#define HID  128
#define NC   47
#define NCP  48
#define EMAX 2000000
#define NB   ((NN + 255) / 256)

// ---------------- scratch (device globals) ----------------------------------
__device__ float g_xw [(size_t)NN * HID];
__device__ float g_h  [(size_t)NN * HID];
__device__ float g_hw [(size_t)NN * NCP];
__device__ float g_dinv[NN];
__device__ int   g_cnt [NN];
__device__ int   g_off [NN];
__device__ int   g_cur [NN];
__device__ int   g_csr [EMAX];
__device__ int   g_bsum[512];
__device__ __nv_bfloat16 g_w1t_hi[HID * FIN];   // W1^T split-hi [n=128][k=256]
__device__ __nv_bfloat16 g_w1t_lo[HID * FIN];   // W1^T split-lo

typedef unsigned long long ull;

__device__ __forceinline__ ull pk2(float lo, float hi) {
    ull r; asm("mov.b64 %0,{%1,%2};" : "=l"(r) : "f"(lo), "f"(hi)); return r;
}
__device__ __forceinline__ void unpk2(ull v, float &lo, float &hi) {
    asm("mov.b64 {%0,%1},%2;" : "=f"(lo), "=f"(hi) : "l"(v));
}
__device__ __forceinline__ ull fma2(ull a, ull b, ull c) {
    ull d; asm("fma.rn.f32x2 %0,%1,%2,%3;" : "=l"(d) : "l"(a), "l"(b), "l"(c)); return d;
}
__device__ __forceinline__ void mma_bf16(float *c, const uint32_t *a, const uint32_t *b) {
    asm("mma.sync.aligned.m16n8k16.row.col.f32.bf16.bf16.f32 "
        "{%0,%1,%2,%3}, {%4,%5,%6,%7}, {%8,%9}, {%0,%1,%2,%3};"
        : "+f"(c[0]), "+f"(c[1]), "+f"(c[2]), "+f"(c[3])
        : "r"(a[0]), "r"(a[1]), "r"(a[2]), "r"(a[3]), "r"(b[0]), "r"(b[1]));
}
__device__ __forceinline__ uint32_t bf16x2_of(float f0, float f1) {
    __nv_bfloat162 h = __floats2bfloat162_rn(f0, f1);
    return *reinterpret_cast<uint32_t *>(&h);
}

// ---------------- CSR build --------------------------------------------------
__global__ void k_zero_cnt() {
    int i = blockIdx.x * blockDim.x + threadIdx.x;
    if (i < NN) g_cnt[i] = 0;
}
__global__ void k_hist(const int *__restrict__ dst, int E) {
    int i = blockIdx.x * blockDim.x + threadIdx.x;
    if (i < E) atomicAdd(&g_cnt[dst[i]], 1);
}
__global__ void k_scan1() {
    __shared__ int sh[256];
    int i = blockIdx.x * 256 + threadIdx.x;
    sh[threadIdx.x] = (i < NN) ? g_cnt[i] : 0;
    __syncthreads();
#pragma unroll
    for (int o = 128; o > 0; o >>= 1) {
        if (threadIdx.x < o) sh[threadIdx.x] += sh[threadIdx.x + o];
        __syncthreads();
    }
    if (threadIdx.x == 0) g_bsum[blockIdx.x] = sh[0];
}
__global__ void k_scan2() {
    __shared__ int sh[512];
    int t = threadIdx.x;
    int v = (t < NB) ? g_bsum[t] : 0;
    sh[t] = v;
    __syncthreads();
#pragma unroll
    for (int o = 1; o < 512; o <<= 1) {
        int u = (t >= o) ? sh[t - o] : 0;
        __syncthreads();
        sh[t] += u;
        __syncthreads();
    }
    if (t < NB) g_bsum[t] = sh[t] - v;
}
__global__ void k_scan3() {
    __shared__ int sh[256];
    int t = threadIdx.x;
    int i = blockIdx.x * 256 + t;
    int v = (i < NN) ? g_cnt[i] : 0;
    sh[t] = v;
    __syncthreads();
#pragma unroll
    for (int o = 1; o < 256; o <<= 1) {
        int u = (t >= o) ? sh[t - o] : 0;
        __syncthreads();
        sh[t] += u;
        __syncthreads();
    }
    if (i < NN) {
        int ex = g_bsum[blockIdx.x] + sh[t] - v;
        g_off[i] = ex;
        g_cur[i] = ex;
        g_dinv[i] = rsqrtf((float)(v + 1));
    }
}
__global__ void k_fill(const int *__restrict__ src, const int *__restrict__ dst, int E) {
    int i = blockIdx.x * blockDim.x + threadIdx.x;
    if (i < E) {
        int pos = atomicAdd(&g_cur[dst[i]], 1);
        g_csr[pos] = src[i];
    }
}

// ---------------- W1 prep: transpose + bf16 split ---------------------------
__global__ void k_w1prep(const float *__restrict__ W1) {
    int i = blockIdx.x * blockDim.x + threadIdx.x;
    if (i >= HID * FIN) return;
    int n = i >> 8;
    int k = i & 255;
    float x = W1[(size_t)k * HID + n];
    __nv_bfloat16 h = __float2bfloat16(x);
    g_w1t_hi[i] = h;
    g_w1t_lo[i] = __float2bfloat16(x - __bfloat162float(h));
}

// ---------------- GEMM1: bf16-split 3-pass, B smem-resident, A pipelined ----
// Block 128x128, BK=32 (8 chunks), 8 warps (4x2), warp tile 32x64.
#define BPITCH 132                       // words per B row (128 + 4 pad)
#define APITCH2 20                       // words per A row (16 + 4 pad)
#define B_WORDS (128 * BPITCH)           // 16896 per hi/lo
#define A_WORDS (128 * APITCH2)          // 2560 per tile
#define G1_SMEM ((2 * B_WORDS + 4 * A_WORDS) * 4)   // 176128 bytes

__global__ __launch_bounds__(256, 1) void k_gemm1_mma(const float *__restrict__ X) {
    extern __shared__ uint32_t sm[];
    uint32_t *bHi = sm;
    uint32_t *bLo = sm + B_WORDS;
    uint32_t *aBuf = sm + 2 * B_WORDS;   // [s][hi|lo] each A_WORDS

    const int tid  = threadIdx.x;
    const int wid  = tid >> 5, lane = tid & 31;
    const int g    = lane >> 2, tig = lane & 3;
    const int wM   = (wid & 3) * 32;
    const int wN   = (wid >> 2) * 64;
    const int m0   = blockIdx.x * 128;

    // ---- load whole B (hi/lo) into smem: 4096 uint4 each ----
#pragma unroll
    for (int it = 0; it < 16; it++) {
        int q = tid + it * 256;
        int row = q >> 5, c4 = q & 31;
        size_t gi = (size_t)row * FIN + c4 * 8;
        *reinterpret_cast<uint4 *>(&bHi[row * BPITCH + c4 * 4]) =
            *reinterpret_cast<const uint4 *>(&g_w1t_hi[gi]);
        *reinterpret_cast<uint4 *>(&bLo[row * BPITCH + c4 * 4]) =
            *reinterpret_cast<const uint4 *>(&g_w1t_lo[gi]);
    }

    float acc[2][8][4];
#pragma unroll
    for (int i = 0; i < 2; i++)
#pragma unroll
        for (int j = 0; j < 8; j++)
#pragma unroll
            for (int l = 0; l < 4; l++) acc[i][j][l] = 0.f;

    float4 stg[4];
#pragma unroll
    for (int it = 0; it < 4; it++) {             // prologue: LDG chunk 0
        int q = tid + it * 256;
        int row = q >> 3, c4 = q & 7;
        int grow = m0 + row;
        stg[it] = make_float4(0.f, 0.f, 0.f, 0.f);
        if (grow < NN)
            stg[it] = *reinterpret_cast<const float4 *>(&X[(size_t)grow * FIN + c4 * 4]);
    }
    {
        uint32_t *aHi = aBuf, *aLo = aBuf + A_WORDS;
#pragma unroll
        for (int it = 0; it < 4; it++) {
            int q = tid + it * 256;
            int row = q >> 3, c4 = q & 7;
            float4 v = stg[it];
            float hx = __bfloat162float(__float2bfloat16(v.x));
            float hy = __bfloat162float(__float2bfloat16(v.y));
            float hz = __bfloat162float(__float2bfloat16(v.z));
            float hw = __bfloat162float(__float2bfloat16(v.w));
            int o = row * APITCH2 + c4 * 2;
            aHi[o]     = bf16x2_of(hx, hy);
            aHi[o + 1] = bf16x2_of(hz, hw);
            aLo[o]     = bf16x2_of(v.x - hx, v.y - hy);
            aLo[o + 1] = bf16x2_of(v.z - hz, v.w - hw);
        }
    }
    __syncthreads();

    for (int ch = 0; ch < 8; ch++) {             // 8 K-chunks of 32
        // ---- prefetch next chunk to registers (overlaps with MMA below) ----
        if (ch < 7) {
#pragma unroll
            for (int it = 0; it < 4; it++) {
                int q = tid + it * 256;
                int row = q >> 3, c4 = q & 7;
                int grow = m0 + row;
                stg[it] = make_float4(0.f, 0.f, 0.f, 0.f);
                if (grow < NN)
                    stg[it] = *reinterpret_cast<const float4 *>(
                        &X[(size_t)grow * FIN + (ch + 1) * 32 + c4 * 4]);
            }
        }

        // ---- MMA on current buffer (pass-outer: acc reuse distance = 16) ----
        uint32_t *aHi = aBuf + (ch & 1) * 2 * A_WORDS;
        uint32_t *aLo = aHi + A_WORDS;
#pragma unroll
        for (int k16 = 0; k16 < 2; k16++) {
            const int kw = k16 * 8;
            uint32_t Ah[2][4], Al[2][4], Bh[8][2], Bl[8][2];
#pragma unroll
            for (int ma = 0; ma < 2; ma++) {
                int r0 = (wM + ma * 16 + g) * APITCH2 + kw + tig;
                int r1 = r0 + 8 * APITCH2;
                Ah[ma][0] = aHi[r0]; Ah[ma][1] = aHi[r1];
                Ah[ma][2] = aHi[r0 + 4]; Ah[ma][3] = aHi[r1 + 4];
                Al[ma][0] = aLo[r0]; Al[ma][1] = aLo[r1];
                Al[ma][2] = aLo[r0 + 4]; Al[ma][3] = aLo[r1 + 4];
            }
#pragma unroll
            for (int na = 0; na < 8; na++) {
                int b0 = (wN + na * 8 + g) * BPITCH + ch * 16 + kw + tig;
                Bh[na][0] = bHi[b0]; Bh[na][1] = bHi[b0 + 4];
                Bl[na][0] = bLo[b0]; Bl[na][1] = bLo[b0 + 4];
            }
            // pass 1: Ah*Bh over all 16 accumulators
#pragma unroll
            for (int ma = 0; ma < 2; ma++)
#pragma unroll
                for (int na = 0; na < 8; na++)
                    mma_bf16(acc[ma][na], Ah[ma], Bh[na]);
            // pass 2: Ah*Bl
#pragma unroll
            for (int ma = 0; ma < 2; ma++)
#pragma unroll
                for (int na = 0; na < 8; na++)
                    mma_bf16(acc[ma][na], Ah[ma], Bl[na]);
            // pass 3: Al*Bh
#pragma unroll
            for (int ma = 0; ma < 2; ma++)
#pragma unroll
                for (int na = 0; na < 8; na++)
                    mma_bf16(acc[ma][na], Al[ma], Bh[na]);
        }

        // ---- convert + store next chunk into the other buffer ----
        if (ch < 7) {
            uint32_t *nHi = aBuf + ((ch + 1) & 1) * 2 * A_WORDS;
            uint32_t *nLo = nHi + A_WORDS;
#pragma unroll
            for (int it = 0; it < 4; it++) {
                int q = tid + it * 256;
                int row = q >> 3, c4 = q & 7;
                float4 v = stg[it];
                float hx = __bfloat162float(__float2bfloat16(v.x));
                float hy = __bfloat162float(__float2bfloat16(v.y));
                float hz = __bfloat162float(__float2bfloat16(v.z));
                float hw = __bfloat162float(__float2bfloat16(v.w));
                int o = row * APITCH2 + c4 * 2;
                nHi[o]     = bf16x2_of(hx, hy);
                nHi[o + 1] = bf16x2_of(hz, hw);
                nLo[o]     = bf16x2_of(v.x - hx, v.y - hy);
                nLo[o + 1] = bf16x2_of(v.z - hz, v.w - hw);
            }
            __syncthreads();
        }
    }

    // ---- epilogue ----
#pragma unroll
    for (int ma = 0; ma < 2; ma++) {
        int row0 = m0 + wM + ma * 16 + g;
        int row1 = row0 + 8;
#pragma unroll
        for (int na = 0; na < 8; na++) {
            int col = wN + na * 8 + tig * 2;
            if (row0 < NN)
                *reinterpret_cast<float2 *>(&g_xw[(size_t)row0 * HID + col]) =
                    make_float2(acc[ma][na][0], acc[ma][na][1]);
            if (row1 < NN)
                *reinterpret_cast<float2 *>(&g_xw[(size_t)row1 * HID + col]) =
                    make_float2(acc[ma][na][2], acc[ma][na][3]);
        }
    }
}

// ---------------- gather layer 1 (warp/node) + self + bias + relu -----------
__global__ __launch_bounds__(256) void k_gather1(const float *__restrict__ b1) {
    int w = (blockIdx.x * blockDim.x + threadIdx.x) >> 5;
    int lane = threadIdx.x & 31;
    if (w >= NN) return;
    float dw = g_dinv[w];
    int beg = g_off[w], n = g_cnt[w];

    float cs = dw * dw;
    float4 a0 = *reinterpret_cast<const float4 *>(&g_xw[(size_t)w * HID + lane * 4]);
    a0.x *= cs; a0.y *= cs; a0.z *= cs; a0.w *= cs;
    float4 a1 = make_float4(0.f, 0.f, 0.f, 0.f);

    int j = 0;
    for (; j + 2 <= n; j += 2) {
        int s0 = __ldg(&g_csr[beg + j]);
        int s1 = __ldg(&g_csr[beg + j + 1]);
        float c0 = __ldg(&g_dinv[s0]) * dw;
        float c1 = __ldg(&g_dinv[s1]) * dw;
        float4 v0 = *reinterpret_cast<const float4 *>(&g_xw[(size_t)s0 * HID + lane * 4]);
        float4 v1 = *reinterpret_cast<const float4 *>(&g_xw[(size_t)s1 * HID + lane * 4]);
        a0.x = fmaf(v0.x, c0, a0.x); a0.y = fmaf(v0.y, c0, a0.y);
        a0.z = fmaf(v0.z, c0, a0.z); a0.w = fmaf(v0.w, c0, a0.w);
        a1.x = fmaf(v1.x, c1, a1.x); a1.y = fmaf(v1.y, c1, a1.y);
        a1.z = fmaf(v1.z, c1, a1.z); a1.w = fmaf(v1.w, c1, a1.w);
    }
    if (j < n) {
        int s0 = __ldg(&g_csr[beg + j]);
        float c0 = __ldg(&g_dinv[s0]) * dw;
        float4 v0 = *reinterpret_cast<const float4 *>(&g_xw[(size_t)s0 * HID + lane * 4]);
        a0.x = fmaf(v0.x, c0, a0.x); a0.y = fmaf(v0.y, c0, a0.y);
        a0.z = fmaf(v0.z, c0, a0.z); a0.w = fmaf(v0.w, c0, a0.w);
    }
    float4 b = reinterpret_cast<const float4 *>(b1)[lane];
    float4 r;
    r.x = fmaxf(a0.x + a1.x + b.x, 0.f);
    r.y = fmaxf(a0.y + a1.y + b.y, 0.f);
    r.z = fmaxf(a0.z + a1.z + b.z, 0.f);
    r.w = fmaxf(a0.w + a1.w + b.w, 0.f);
    *reinterpret_cast<float4 *>(&g_h[(size_t)w * HID + lane * 4]) = r;
}

// ---------------- GEMM2: g_hw = h[NN,128] @ W2[128,47] (padded 48) ----------
__global__ __launch_bounds__(256) void k_gemm2(const float *__restrict__ W2) {
    __shared__ float As[16][128];
    __shared__ float Bs[16][48];
    const int tid = threadIdx.x;
    const int m0  = blockIdx.x * 128;
    const int ty  = tid >> 3;
    const int tx  = tid & 7;

    ull acc[4][3];
#pragma unroll
    for (int i = 0; i < 4; i++)
#pragma unroll
        for (int j = 0; j < 3; j++) acc[i][j] = 0ull;

    for (int kt = 0; kt < HID; kt += 16) {
#pragma unroll
        for (int l = 0; l < 2; l++) {
            int q = tid + l * 256;
            int r = q >> 2, c4 = q & 3;
            int row = m0 + r;
            float4 v = make_float4(0.f, 0.f, 0.f, 0.f);
            if (row < NN)
                v = *reinterpret_cast<const float4 *>(&g_h[(size_t)row * HID + kt + c4 * 4]);
            As[c4 * 4 + 0][r] = v.x; As[c4 * 4 + 1][r] = v.y;
            As[c4 * 4 + 2][r] = v.z; As[c4 * 4 + 3][r] = v.w;
        }
#pragma unroll
        for (int l = 0; l < 3; l++) {
            int q = tid + l * 256;
            int k = q / 48, c = q % 48;
            Bs[k][c] = (c < NC) ? W2[(size_t)(kt + k) * NC + c] : 0.f;
        }
        __syncthreads();
#pragma unroll
        for (int kk = 0; kk < 16; kk++) {
            float4 a = *reinterpret_cast<float4 *>(&As[kk][ty * 4]);
            float2 c0 = *reinterpret_cast<float2 *>(&Bs[kk][tx * 6]);
            float2 c1 = *reinterpret_cast<float2 *>(&Bs[kk][tx * 6 + 2]);
            float2 c2 = *reinterpret_cast<float2 *>(&Bs[kk][tx * 6 + 4]);
            ull bb[3] = { pk2(c0.x, c0.y), pk2(c1.x, c1.y), pk2(c2.x, c2.y) };
            float av[4] = { a.x, a.y, a.z, a.w };
#pragma unroll
            for (int i = 0; i < 4; i++) {
                ull aa = pk2(av[i], av[i]);
#pragma unroll
                for (int jj = 0; jj < 3; jj++) acc[i][jj] = fma2(aa, bb[jj], acc[i][jj]);
            }
        }
        __syncthreads();
    }
#pragma unroll
    for (int i = 0; i < 4; i++) {
        int row = m0 + ty * 4 + i;
        if (row < NN) {
            float o0, o1, o2, o3, o4, o5;
            unpk2(acc[i][0], o0, o1); unpk2(acc[i][1], o2, o3); unpk2(acc[i][2], o4, o5);
            float *p = &g_hw[(size_t)row * NCP + tx * 6];
            *reinterpret_cast<float2 *>(p)     = make_float2(o0, o1);
            *reinterpret_cast<float2 *>(p + 2) = make_float2(o2, o3);
            *reinterpret_cast<float2 *>(p + 4) = make_float2(o4, o5);
        }
    }
}

// ---------------- gather layer 2 + bias + log_softmax -----------------------
__global__ __launch_bounds__(256) void k_gather2(const float *__restrict__ b2,
                                                 float *__restrict__ out) {
    int w = (blockIdx.x * blockDim.x + threadIdx.x) >> 5;
    int lane = threadIdx.x & 31;
    if (w >= NN) return;
    float dw = g_dinv[w];
    int beg = g_off[w], n = g_cnt[w];

    int grp = lane / 12;
    int col = lane - grp * 12;

    float4 acc = make_float4(0.f, 0.f, 0.f, 0.f);
    if (lane < 12) {
        float cs = dw * dw;
        float4 v = *reinterpret_cast<const float4 *>(&g_hw[(size_t)w * NCP + lane * 4]);
        acc = make_float4(v.x * cs, v.y * cs, v.z * cs, v.w * cs);
    }
    for (int j = 0; j < n; j += 2) {
        int e = j + grp;
        if (grp < 2 && e < n) {
            int s = __ldg(&g_csr[beg + e]);
            float c = __ldg(&g_dinv[s]) * dw;
            float4 v = *reinterpret_cast<const float4 *>(&g_hw[(size_t)s * NCP + col * 4]);
            acc.x = fmaf(v.x, c, acc.x);
            acc.y = fmaf(v.y, c, acc.y);
            acc.z = fmaf(v.z, c, acc.z);
            acc.w = fmaf(v.w, c, acc.w);
        }
    }
    acc.x += __shfl_sync(0xffffffffu, acc.x, (lane + 12) & 31);
    acc.y += __shfl_sync(0xffffffffu, acc.y, (lane + 12) & 31);
    acc.z += __shfl_sync(0xffffffffu, acc.z, (lane + 12) & 31);
    acc.w += __shfl_sync(0xffffffffu, acc.w, (lane + 12) & 31);

    float zx = 0.f, zy = 0.f, zz = 0.f, zw = 0.f;
    bool act = (lane < 12);
    bool hasw = (lane < 11);
    if (act) {
        int c0 = lane * 4;
        zx = acc.x + b2[c0];
        zy = acc.y + b2[c0 + 1];
        zz = acc.z + b2[c0 + 2];
        zw = hasw ? (acc.w + b2[c0 + 3]) : -1e30f;
    }
    float m = act ? fmaxf(fmaxf(zx, zy), fmaxf(zz, zw)) : -1e30f;
#pragma unroll
    for (int o = 16; o > 0; o >>= 1)
        m = fmaxf(m, __shfl_xor_sync(0xffffffffu, m, o));
    float s = 0.f;
    if (act) s = expf(zx - m) + expf(zy - m) + expf(zz - m) + (hasw ? expf(zw - m) : 0.f);
#pragma unroll
    for (int o = 16; o > 0; o >>= 1)
        s += __shfl_xor_sync(0xffffffffu, s, o);
    float ls = logf(s) + m;
    if (act) {
        float *p = &out[(size_t)w * NC + lane * 4];
        p[0] = zx - ls;
        p[1] = zy - ls;
        p[2] = zz - ls;
        if (hasw) p[3] = zw - ls;
    }
}

// ---------------- launch ----------------------------------------------------
extern "C" void kernel_launch(void *const *d_in, const int *in_sizes, int n_in,
                              void *d_out, int out_size) {
    const float *x  = (const float *)d_in[0];
    const int   *ei = (const int   *)d_in[1];
    const float *W1 = (const float *)d_in[2];
    const float *b1 = (const float *)d_in[3];
    const float *W2 = (const float *)d_in[4];
    const float *b2 = (const float *)d_in[5];
    float *out = (float *)d_out;

    const int E = in_sizes[1] / 2;
    const int *src = ei;
    const int *dst = ei + E;

    cudaFuncSetAttribute(k_gemm1_mma, cudaFuncAttributeMaxDynamicSharedMemorySize, G1_SMEM);

    k_zero_cnt<<<NB, 256>>>();                                   // 1
    k_hist<<<(E + 255) / 256, 256>>>(dst, E);                    // 2
    k_w1prep<<<(HID * FIN + 255) / 256, 256>>>(W1);              // 3
    k_gemm1_mma<<<(NN + 127) / 128, 256, G1_SMEM>>>(x);          // 4 <- profiled
    k_scan1<<<NB, 256>>>();                                      // 5
    k_scan2<<<1, 512>>>();                                       // 6
    k_scan3<<<NB, 256>>>();                                      // 7
    k_fill<<<(E + 255) / 256, 256>>>(src, dst, E);               // 8
    k_gather1<<<(NN * 32 + 255) / 256, 256>>>(b1);               // 9
    k_gemm2<<<(NN + 127) / 128, 256>>>(W2);                      // 10
    k_gather2<<<(NN * 32 + 255) / 256, 256>>>(b2, out);          // 11
}